// round 14
// baseline (speedup 1.0000x reference)
#include <cuda_runtime.h>
#include <cuda_bf16.h>

// Batched 1D linear interpolation with clamped extrapolation.
// t: [B, N] sorted per row, v: [B, N], r: [B, M]  ->  out: [B, M]
//
// One CTA per row, 64KB dynamic SMEM (3 CTAs/SM). GHOST-KNOT layout:
//   ts[i] = t[i-1], vs[i] = v[i-1], sa[i] = slope[i-1]  for i in [1, NN-1],
//   with duplicated boundary knots ts[0]=t[0] (slope 0) and ts[NN]=t[NN-1]
//   (slope 0), and a +inf walk sentinel at ts[NN+1]. The searchsorted
//   position pos in [0, NN] is then DIRECTLY the fetch index:
//     out = fmaf(r - ts[pos], sa[pos], vs[pos])
//   pos=0  -> vfirst (lower clamp), pos=NN -> vlast (upper clamp), interior
//   -> exact interpolation. No clamps, no selects, no boundary registers.
//   Split packed f32 arrays (random SMEM gathers must be 4-byte, all-bank).
//
//   P[k] = u16 bucket table, KB=8063 uniform buckets over [tmin,tmax];
//   bits[0:14] = searchsorted pos of bucket left edge; bit 15 = PURE
//   (bucket knot-free -> pos exact, walk skipped; ~60% of queries).
//
// LINEAR-WALK: advance while t_orig[pos] <= r, i.e. probe (ts+1)[pos] --
// the +1 folds into the base pointer. 3 fixed branchless rounds (parked
// lanes broadcast) + rarely-entered warp-voted fallback (correct for ANY
// sorted t; sentinel bounds the walk).
//
// FUSED PROLOGUE: staging (shifted via shuffles), slopes, and the flagged
// bucket scatter in ONE register-resident pass; scatter ranges tile
// [0, KB-1] -> no fill pass.

#define NN 4096
#define MM 4096
#define KB 8063
#define TABLE (KB + 1)
#define THREADS 512
#define QPT (MM / THREADS)           // 8 queries per thread
#define PURE 0x8000u

#define OFF_TS 0                           // (NN+2) floats = 16392 B
#define OFF_VS 16416
#define OFF_SA 32832
#define OFF_P  49248
#define SMEM_BYTES (OFF_P + TABLE * 2)     // 65376

__device__ __forceinline__ float seg_slope(float t0, float t1, float v0, float v1) {
    float d = t1 - t0;
    float denom = (d == 0.0f) ? 1.0f : d;
    return __fdividef(v1 - v0, denom);
}

__global__ __launch_bounds__(THREADS, 3)
void interp1d_kernel(const float* __restrict__ t,
                     const float* __restrict__ v,
                     const float* __restrict__ r,
                     float* __restrict__ out) {
    extern __shared__ char smem[];
    float*          ts = reinterpret_cast<float*>(smem + OFF_TS);
    float*          vs = reinterpret_cast<float*>(smem + OFF_VS);
    float*          sa = reinterpret_cast<float*>(smem + OFF_SA);
    unsigned short* P  = reinterpret_cast<unsigned short*>(smem + OFF_P);

    const int row = blockIdx.x;
    const float* trow = t + (size_t)row * NN;
    const float* vrow = v + (size_t)row * NN;
    const float* rrow = r + (size_t)row * MM;
    float*       orow = out + (size_t)row * MM;
    const int tid  = threadIdx.x;
    const int lane = tid & 31;

    // Uniform scalar loads (same address across warp -> broadcast)
    const float tmin   = trow[0];
    const float tmax   = trow[NN - 1];
    const float vlast  = vrow[NN - 1];
    const float span   = tmax - tmin;
    const bool  ok     = (span > 0.0f);
    const float scale  = ok ? (float)KB / span : 0.0f;
    const float bias   = -tmin * scale;

    auto bucket_of = [&](float x) -> int {
        int k = (int)fmaf(x, scale, bias);   // monotone nondecreasing in x
        k = (k < 0) ? 0 : k;
        k = (k > KB - 1) ? KB - 1 : k;
        return k;
    };

    // scatter for knot e owning table range (p, c]: interior entries are
    // knot-free buckets -> PURE; entry c holds knot e -> walk required.
    auto scat = [&](int e, int p, int c) {
        unsigned short pe = (unsigned short)(e | PURE);
        for (int k = p + 1; k < c; k++) P[k] = pe;
        if (c > p) P[c] = (unsigned short)e;
    };

    // ---- Fused staging (shifted ghost layout) + slopes + scatter ----
    const float4* t4 = reinterpret_cast<const float4*>(trow);
    const float4* v4 = reinterpret_cast<const float4*>(vrow);
    float4* ts4 = reinterpret_cast<float4*>(ts);
    float4* vs4 = reinterpret_cast<float4*>(vs);
    float4* sa4 = reinterpret_cast<float4*>(sa);

    #pragma unroll
    for (int i = 0; i < NN / 4 / THREADS; i++) {       // 2 iterations
        int i4   = tid + i * THREADS;
        int base = i4 * 4;
        float4 a = t4[i4];
        float4 b = v4[i4];

        // neighbors via shuffle; warp-edge lanes via (cached) LDG
        float tn = __shfl_down_sync(0xffffffffu, a.x, 1);
        float vn = __shfl_down_sync(0xffffffffu, b.x, 1);
        if (lane == 31) {
            if (base + 4 < NN) { tn = trow[base + 4]; vn = vrow[base + 4]; }
            else               { tn = a.w;            vn = b.w; }
        }
        float tp = __shfl_up_sync(0xffffffffu, a.w, 1);
        float vp = __shfl_up_sync(0xffffffffu, b.w, 1);
        if (lane == 0) {
            if (base > 0) { tp = trow[base - 1]; vp = vrow[base - 1]; }
            else          { tp = a.x;            vp = b.x; }
        }

        float4 s;                                      // slopes base..base+3
        s.x = seg_slope(a.x, a.y, b.x, b.y);
        s.y = seg_slope(a.y, a.z, b.y, b.z);
        s.z = seg_slope(a.z, a.w, b.z, b.w);
        s.w = seg_slope(a.w, tn,  b.w, vn);
        float sp = __shfl_up_sync(0xffffffffu, s.w, 1); // slope base-1
        if (lane == 0)
            sp = (base > 0) ? seg_slope(tp, a.x, vp, b.x) : 0.0f;

        // shifted stores: element i of each array = knot i-1 (aligned f4)
        ts4[i4] = make_float4(tp, a.x, a.y, a.z);
        vs4[i4] = make_float4(vp, b.x, b.y, b.z);
        sa4[i4] = make_float4(sp, s.x, s.y, s.z);

        if (ok) {
            int bprev = (base == 0) ? -1 : bucket_of(tp);
            int b0 = bucket_of(a.x);
            int b1 = bucket_of(a.y);
            int b2 = bucket_of(a.z);
            int b3 = bucket_of(a.w);
            scat(base + 0, bprev, b0);
            scat(base + 1, b0,    b1);
            scat(base + 2, b1,    b2);
            scat(base + 3, b2,    b3);
        }
    }
    if (tid == 0) {
        ts[NN]     = tmax;                              // ghost upper knot
        ts[NN + 1] = __int_as_float(0x7f800000);        // +inf walk sentinel
        vs[NN]     = vlast;
        sa[NN]     = 0.0f;                              // -> out = vlast
    }
    if (!ok) {
        // degenerate row (all knots equal): pos = NN, PURE -> vlast path
        unsigned int* P32 = reinterpret_cast<unsigned int*>(P);
        const unsigned int e = (unsigned)NN | PURE;
        const unsigned int fill = (e << 16) | e;
        for (int j = tid; j < TABLE / 2; j += THREADS) P32[j] = fill;
    }
    __syncthreads();

    // walk probes t_orig[pos] = ts[pos+1]; fold +1 into the base pointer
    const float* tsw = ts + 1;

    // ---- Queries: 8 per thread, 4 register-interleaved at a time ----
    const float4* r4 = reinterpret_cast<const float4*>(rrow);
    float4*       o4 = reinterpret_cast<float4*>(orow);

    #pragma unroll
    for (int b = 0; b < QPT / 4; b++) {
        float4 rq = r4[tid + b * THREADS];             // 1 LDG.128, coalesced
        float rv[4] = {rq.x, rq.y, rq.z, rq.w};

        int  pos[4];
        bool act[4];
        #pragma unroll
        for (int q = 0; q < 4; q++) {
            unsigned int lh = P[bucket_of(rv[q])];     // ONE table read/query
            pos[q] = (int)(lh & 0x7FFFu);
            act[q] = (lh & PURE) == 0u;                // pure -> walk skipped
        }

        // 3 fixed branchless walk rounds; inactive lanes park (broadcast)
        #pragma unroll
        for (int rnd = 0; rnd < 3; rnd++) {
            #pragma unroll
            for (int q = 0; q < 4; q++) {
                int addr = act[q] ? pos[q] : 0;        // pos <= NN (sentinel)
                float tm = tsw[addr];
                bool adv = act[q] && (tm <= rv[q]);
                pos[q] += adv ? 1 : 0;
                act[q]  = adv;
            }
        }

        // voted fallback (correct for any sorted t; sentinel bounds walk)
        while (__any_sync(0xffffffffu, act[0] | act[1] | act[2] | act[3])) {
            #pragma unroll
            for (int q = 0; q < 4; q++) {
                int addr = act[q] ? pos[q] : 0;
                float tm = tsw[addr];
                bool adv = act[q] && (tm <= rv[q]);
                pos[q] += adv ? 1 : 0;
                act[q]  = adv;
            }
        }

        // ghost layout: pos IS the fetch index; no clamps, no selects
        float res[4];
        #pragma unroll
        for (int q = 0; q < 4; q++) {
            int p = pos[q];
            float t0 = ts[p];                          // 3 random LDS.32,
            float v0 = vs[p];                          // all-bank spread
            float s  = sa[p];
            res[q] = fmaf(rv[q] - t0, s, v0);
        }

        o4[tid + b * THREADS] = make_float4(res[0], res[1], res[2], res[3]);
    }
}

extern "C" void kernel_launch(void* const* d_in, const int* in_sizes, int n_in,
                              void* d_out, int out_size) {
    const float* t = (const float*)d_in[0];
    const float* v = (const float*)d_in[1];
    const float* r = (const float*)d_in[2];
    float* out = (float*)d_out;

    cudaFuncSetAttribute(interp1d_kernel,
                         cudaFuncAttributeMaxDynamicSharedMemorySize, SMEM_BYTES);

    int B = in_sizes[0] / NN;   // 2048 for the reference shape
    interp1d_kernel<<<B, THREADS, SMEM_BYTES>>>(t, v, r, out);
}